// round 8
// baseline (speedup 1.0000x reference)
#include <cuda_runtime.h>

// DenseGATBlock: 2-layer GAT, N=8192, D=128, heads=1, sparse adj (~1% + self loops).
// R6 = R4 design with the REAL alignment fix: __align__(16) on shared arrays
// accessed via float4. (Fused kernel merged csr_body's `__shared__ int cnt`
// into the same shared layout as As/Bs; cnt at offset 0 pushed As to offset 4
// -> misaligned 16B shared stores.)

#define NN 8192
#define DD 128
#define MAXDEG 256
#define BM 64
#define BK 32
#define GEMM_BLOCKS (NN / BM)   // 128

// Scratch (device globals; no allocation allowed)
__device__ int   g_col[NN * MAXDEG];              // 8 MB padded neighbor lists
__device__ int   g_deg[NN];
__device__ __align__(16) float g_h[NN * DD];      // 4 MB, L2-resident
__device__ float g_asrc[NN];
__device__ float g_adst[NN];

// ---------------------------------------------------------------------------
// CSR build body: one block per row, 256 threads. Reads adj row (32 KB) once.
// ---------------------------------------------------------------------------
__device__ __forceinline__ void csr_body(const float* __restrict__ adj, int i) {
    __shared__ int cnt;
    if (threadIdx.x == 0) cnt = 0;
    __syncthreads();
    const float4* row = (const float4*)(adj + (size_t)i * NN);
    int* outc = g_col + i * MAXDEG;
    for (int v = threadIdx.x; v < NN / 4; v += blockDim.x) {
        float4 f = row[v];
        int base = v * 4;
        if (f.x != 0.f) { int p = atomicAdd(&cnt, 1); if (p < MAXDEG) outc[p] = base; }
        if (f.y != 0.f) { int p = atomicAdd(&cnt, 1); if (p < MAXDEG) outc[p] = base + 1; }
        if (f.z != 0.f) { int p = atomicAdd(&cnt, 1); if (p < MAXDEG) outc[p] = base + 2; }
        if (f.w != 0.f) { int p = atomicAdd(&cnt, 1); if (p < MAXDEG) outc[p] = base + 3; }
    }
    __syncthreads();
    if (threadIdx.x == 0) g_deg[i] = cnt < MAXDEG ? cnt : MAXDEG;
}

// ---------------------------------------------------------------------------
// GEMM body: h[64,128] tile = A@W, 256 threads, 8x4 register tile.
// Epilogue: fused attention scores a_src/a_dst via warp shuffle reduce.
// ---------------------------------------------------------------------------
__device__ __forceinline__ void gemm_body(const float* __restrict__ A,
                                          const float* __restrict__ W,
                                          const float* __restrict__ att_src,
                                          const float* __restrict__ att_dst,
                                          float* __restrict__ C,
                                          int rowBase) {
    __shared__ __align__(16) float As[BM][BK];   // 8 KB, float4-accessed
    __shared__ __align__(16) float Bs[BK][DD];   // 16 KB, float4-accessed
    int tid = threadIdx.x;
    int trow = tid >> 5;           // 0..7 (uniform across warp)
    int tcol = tid & 31;           // 0..31
    float acc[8][4];
#pragma unroll
    for (int a = 0; a < 8; a++)
#pragma unroll
        for (int b = 0; b < 4; b++) acc[a][b] = 0.f;

    for (int k0 = 0; k0 < DD; k0 += BK) {
#pragma unroll
        for (int v = 0; v < 2; v++) {
            int f = tid * 2 + v;
            int r = f >> 3, cc = (f & 7) * 4;
            *(float4*)&As[r][cc] =
                *(const float4*)&A[(size_t)(rowBase + r) * DD + k0 + cc];
        }
#pragma unroll
        for (int v = 0; v < 4; v++) {
            int f = tid * 4 + v;
            int r = f >> 5, cc = (f & 31) * 4;
            *(float4*)&Bs[r][cc] = *(const float4*)&W[(k0 + r) * DD + cc];
        }
        __syncthreads();
#pragma unroll
        for (int kk = 0; kk < BK; kk++) {
            float a[8];
#pragma unroll
            for (int ii = 0; ii < 8; ii++) a[ii] = As[trow * 8 + ii][kk];
            float4 bv = *(float4*)&Bs[kk][tcol * 4];
#pragma unroll
            for (int ii = 0; ii < 8; ii++) {
                acc[ii][0] += a[ii] * bv.x;
                acc[ii][1] += a[ii] * bv.y;
                acc[ii][2] += a[ii] * bv.z;
                acc[ii][3] += a[ii] * bv.w;
            }
        }
        __syncthreads();
    }

    // write h tile
#pragma unroll
    for (int ii = 0; ii < 8; ii++) {
        float4 o = make_float4(acc[ii][0], acc[ii][1], acc[ii][2], acc[ii][3]);
        *(float4*)&C[(size_t)(rowBase + trow * 8 + ii) * DD + tcol * 4] = o;
    }

    // fused attention scores: per-row dot with att vectors, warp reduce
    float as0 = att_src[tcol * 4 + 0], as1 = att_src[tcol * 4 + 1];
    float as2 = att_src[tcol * 4 + 2], as3 = att_src[tcol * 4 + 3];
    float ad0 = att_dst[tcol * 4 + 0], ad1 = att_dst[tcol * 4 + 1];
    float ad2 = att_dst[tcol * 4 + 2], ad3 = att_dst[tcol * 4 + 3];
#pragma unroll
    for (int ii = 0; ii < 8; ii++) {
        float s = acc[ii][0] * as0 + acc[ii][1] * as1 +
                  acc[ii][2] * as2 + acc[ii][3] * as3;
        float d = acc[ii][0] * ad0 + acc[ii][1] * ad1 +
                  acc[ii][2] * ad2 + acc[ii][3] * ad3;
#pragma unroll
        for (int o = 16; o; o >>= 1) {
            s += __shfl_xor_sync(0xffffffffu, s, o);
            d += __shfl_xor_sync(0xffffffffu, d, o);
        }
        if (tcol == 0) {
            int row = rowBase + trow * 8 + ii;
            g_asrc[row] = s;
            g_adst[row] = d;
        }
    }
}

// Fused kernel: blocks [0,128) do GEMM tiles, blocks [128, 128+8192) do CSR rows.
__global__ void fused_csr_gemm_k(const float* __restrict__ adj,
                                 const float* __restrict__ A,
                                 const float* __restrict__ W,
                                 const float* __restrict__ att_src,
                                 const float* __restrict__ att_dst,
                                 float* __restrict__ C) {
    if (blockIdx.x < GEMM_BLOCKS)
        gemm_body(A, W, att_src, att_dst, C, blockIdx.x * BM);
    else
        csr_body(adj, blockIdx.x - GEMM_BLOCKS);
}

// Layer-1 GEMM (CSR already built)
__global__ void gemm_k(const float* __restrict__ A, const float* __restrict__ W,
                       const float* __restrict__ att_src,
                       const float* __restrict__ att_dst,
                       float* __restrict__ C) {
    gemm_body(A, W, att_src, att_dst, C, blockIdx.x * BM);
}

// ---------------------------------------------------------------------------
// Aggregate: one block (128 thr = 4 warps) per row.
// Warp w handles edges w, w+4, ...; lane owns channels [4*lane, 4*lane+4).
// ---------------------------------------------------------------------------
__global__ void aggregate_k(const float* __restrict__ h,
                            const float* __restrict__ bias,
                            float* __restrict__ out, int doRelu) {
    int i = blockIdx.x;
    int tid = threadIdx.x;
    int warp = tid >> 5, lane = tid & 31;
    __shared__ int    s_col[MAXDEG];
    __shared__ float  s_w[MAXDEG];
    __shared__ float  s_inv;
    __shared__ __align__(16) float4 s_part[3][32];   // partials from warps 1..3

    int deg = g_deg[i];
    float adsti = g_adst[i];

    // edge scores e = leaky_relu(a_src[j] + a_dst[i])
    for (int j = tid; j < deg; j += 128) {
        int c = g_col[i * MAXDEG + j];
        s_col[j] = c;
        float e = g_asrc[c] + adsti;
        s_w[j] = (e >= 0.f) ? e : 0.2f * e;
    }
    __syncthreads();

    // softmax normalization by warp 0 (shuffle reductions, 2 barriers total)
    if (warp == 0) {
        float m = -1e30f;
        for (int j = lane; j < deg; j += 32) m = fmaxf(m, s_w[j]);
#pragma unroll
        for (int o = 16; o; o >>= 1) m = fmaxf(m, __shfl_xor_sync(0xffffffffu, m, o));
        float sum = 0.f;
        for (int j = lane; j < deg; j += 32) {
            float w = __expf(s_w[j] - m);
            s_w[j] = w;
            sum += w;
        }
#pragma unroll
        for (int o = 16; o; o >>= 1) sum += __shfl_xor_sync(0xffffffffu, sum, o);
        if (lane == 0) s_inv = 1.0f / sum;
    }
    __syncthreads();

    // weighted gather: float4 per lane, 2 independent accumulators per warp
    float4 a0 = make_float4(0.f, 0.f, 0.f, 0.f);
    float4 a1 = make_float4(0.f, 0.f, 0.f, 0.f);
    int j = warp;
    for (; j + 4 < deg; j += 8) {
        float w0 = s_w[j], w1 = s_w[j + 4];
        int   c0 = s_col[j], c1 = s_col[j + 4];
        float4 h0 = *(const float4*)&h[(size_t)c0 * DD + lane * 4];
        float4 h1 = *(const float4*)&h[(size_t)c1 * DD + lane * 4];
        a0.x += w0 * h0.x; a0.y += w0 * h0.y; a0.z += w0 * h0.z; a0.w += w0 * h0.w;
        a1.x += w1 * h1.x; a1.y += w1 * h1.y; a1.z += w1 * h1.z; a1.w += w1 * h1.w;
    }
    if (j < deg) {
        float w0 = s_w[j];
        float4 h0 = *(const float4*)&h[(size_t)s_col[j] * DD + lane * 4];
        a0.x += w0 * h0.x; a0.y += w0 * h0.y; a0.z += w0 * h0.z; a0.w += w0 * h0.w;
    }
    a0.x += a1.x; a0.y += a1.y; a0.z += a1.z; a0.w += a1.w;

    if (warp) s_part[warp - 1][lane] = a0;
    __syncthreads();

    if (warp == 0) {
        float4 p0 = s_part[0][lane], p1 = s_part[1][lane], p2 = s_part[2][lane];
        float inv = s_inv;
        float b0v = bias[lane * 4 + 0], b1v = bias[lane * 4 + 1];
        float b2v = bias[lane * 4 + 2], b3v = bias[lane * 4 + 3];
        float4 o;
        o.x = (a0.x + p0.x + p1.x + p2.x) * inv + b0v;
        o.y = (a0.y + p0.y + p1.y + p2.y) * inv + b1v;
        o.z = (a0.z + p0.z + p1.z + p2.z) * inv + b2v;
        o.w = (a0.w + p0.w + p1.w + p2.w) * inv + b3v;
        if (doRelu) {
            o.x = fmaxf(o.x, 0.f); o.y = fmaxf(o.y, 0.f);
            o.z = fmaxf(o.z, 0.f); o.w = fmaxf(o.w, 0.f);
        }
        *(float4*)&out[(size_t)i * DD + lane * 4] = o;
    }
}

// ---------------------------------------------------------------------------
extern "C" void kernel_launch(void* const* d_in, const int* in_sizes, int n_in,
                              void* d_out, int out_size) {
    const float* x        = (const float*)d_in[0];
    const float* adj      = (const float*)d_in[1];
    const float* W0       = (const float*)d_in[2];
    const float* att_src0 = (const float*)d_in[3];
    const float* att_dst0 = (const float*)d_in[4];
    const float* b0       = (const float*)d_in[5];
    const float* W1       = (const float*)d_in[6];
    const float* att_src1 = (const float*)d_in[7];
    const float* att_dst1 = (const float*)d_in[8];
    const float* b1       = (const float*)d_in[9];

    float* out0 = (float*)d_out;                  // [N,128]
    float* out1 = (float*)d_out + (size_t)NN * DD;

    float* h;
    cudaGetSymbolAddress((void**)&h, g_h);

    // Layer 0: CSR build (DRAM-bound) overlapped with GEMM (compute-bound)
    fused_csr_gemm_k<<<GEMM_BLOCKS + NN, 256>>>(adj, x, W0, att_src0, att_dst0, h);
    aggregate_k<<<NN, 128>>>(h, b0, out0, /*relu=*/1);

    // Layer 1
    gemm_k<<<GEMM_BLOCKS, 256>>>(out0, W1, att_src1, att_dst1, h);
    aggregate_k<<<NN, 128>>>(h, b1, out1, /*relu=*/0);
}

// round 10
// speedup vs baseline: 1.2049x; 1.2049x over previous
#include <cuda_runtime.h>

// DenseGATBlock: 2-layer GAT, N=8192, D=128, heads=1, sparse adj (~1% + self loops).
// R8: CSR scan prefetched (MLP=8) so the fused kernel hits the DRAM floor,
//     GEMM retiled to BM=32 (256 blocks, all SMs busy), aggregate unroll x4.

#define NN 8192
#define DD 128
#define MAXDEG 256
#define BM 32
#define GEMM_BLOCKS (NN / BM)   // 256

// Scratch (device globals; no allocation allowed)
__device__ int   g_col[NN * MAXDEG];              // 8 MB padded neighbor lists
__device__ int   g_deg[NN];
__device__ __align__(16) float g_h[NN * DD];      // 4 MB, L2-resident
__device__ float g_asrc[NN];
__device__ float g_adst[NN];

// ---------------------------------------------------------------------------
// CSR build body: one block per row, 256 threads, prefetch 8 float4/thread
// so all 32 KB of the row is in flight before the compaction work starts.
// ---------------------------------------------------------------------------
__device__ __forceinline__ void csr_body(const float* __restrict__ adj, int i) {
    __shared__ int cnt;
    if (threadIdx.x == 0) cnt = 0;
    __syncthreads();
    const float4* row = (const float4*)(adj + (size_t)i * NN);
    int* outc = g_col + i * MAXDEG;
    int tid = threadIdx.x;

    float4 f[8];
#pragma unroll
    for (int k = 0; k < 8; k++) f[k] = row[tid + k * 256];   // MLP=8

#pragma unroll
    for (int k = 0; k < 8; k++) {
        int base = 4 * (tid + k * 256);
        if (f[k].x != 0.f) { int p = atomicAdd(&cnt, 1); if (p < MAXDEG) outc[p] = base; }
        if (f[k].y != 0.f) { int p = atomicAdd(&cnt, 1); if (p < MAXDEG) outc[p] = base + 1; }
        if (f[k].z != 0.f) { int p = atomicAdd(&cnt, 1); if (p < MAXDEG) outc[p] = base + 2; }
        if (f[k].w != 0.f) { int p = atomicAdd(&cnt, 1); if (p < MAXDEG) outc[p] = base + 3; }
    }
    __syncthreads();
    if (threadIdx.x == 0) g_deg[i] = cnt < MAXDEG ? cnt : MAXDEG;
}

// ---------------------------------------------------------------------------
// GEMM body: h[32,128] tile = A@W, 256 threads, 4x4 register tile.
// Epilogue: fused attention scores a_src/a_dst via warp shuffle reduce.
// ---------------------------------------------------------------------------
#define BK 32
__device__ __forceinline__ void gemm_body(const float* __restrict__ A,
                                          const float* __restrict__ W,
                                          const float* __restrict__ att_src,
                                          const float* __restrict__ att_dst,
                                          float* __restrict__ C,
                                          int rowBase) {
    __shared__ __align__(16) float As[BM][BK];   // 4 KB
    __shared__ __align__(16) float Bs[BK][DD];   // 16 KB
    int tid = threadIdx.x;
    int trow = (tid >> 5) * 4;     // warp -> 4 rows (uniform across warp)
    int tcol = tid & 31;           // 0..31 -> 4 cols
    float acc[4][4];
#pragma unroll
    for (int a = 0; a < 4; a++)
#pragma unroll
        for (int b = 0; b < 4; b++) acc[a][b] = 0.f;

    for (int k0 = 0; k0 < DD; k0 += BK) {
        // As: 32x32 floats = 256 float4, 1 per thread
        {
            int r = tid >> 3, cc = (tid & 7) * 4;
            *(float4*)&As[r][cc] =
                *(const float4*)&A[(size_t)(rowBase + r) * DD + k0 + cc];
        }
        // Bs: 32x128 floats = 1024 float4, 4 per thread, fully coalesced
#pragma unroll
        for (int v = 0; v < 4; v++) {
            int ff = tid + 256 * v;
            int r = ff >> 5, cc = (ff & 31) * 4;
            *(float4*)&Bs[r][cc] = *(const float4*)&W[(k0 + r) * DD + cc];
        }
        __syncthreads();
#pragma unroll
        for (int kk = 0; kk < BK; kk++) {
            float a[4];
#pragma unroll
            for (int ii = 0; ii < 4; ii++) a[ii] = As[trow + ii][kk];  // broadcast
            float4 bv = *(float4*)&Bs[kk][tcol * 4];
#pragma unroll
            for (int ii = 0; ii < 4; ii++) {
                acc[ii][0] += a[ii] * bv.x;
                acc[ii][1] += a[ii] * bv.y;
                acc[ii][2] += a[ii] * bv.z;
                acc[ii][3] += a[ii] * bv.w;
            }
        }
        __syncthreads();
    }

    // write h tile
#pragma unroll
    for (int ii = 0; ii < 4; ii++) {
        float4 o = make_float4(acc[ii][0], acc[ii][1], acc[ii][2], acc[ii][3]);
        *(float4*)&C[(size_t)(rowBase + trow + ii) * DD + tcol * 4] = o;
    }

    // fused attention scores (scalar att loads: alignment-safe)
    float as0 = att_src[tcol * 4 + 0], as1 = att_src[tcol * 4 + 1];
    float as2 = att_src[tcol * 4 + 2], as3 = att_src[tcol * 4 + 3];
    float ad0 = att_dst[tcol * 4 + 0], ad1 = att_dst[tcol * 4 + 1];
    float ad2 = att_dst[tcol * 4 + 2], ad3 = att_dst[tcol * 4 + 3];
#pragma unroll
    for (int ii = 0; ii < 4; ii++) {
        float s = acc[ii][0] * as0 + acc[ii][1] * as1 +
                  acc[ii][2] * as2 + acc[ii][3] * as3;
        float d = acc[ii][0] * ad0 + acc[ii][1] * ad1 +
                  acc[ii][2] * ad2 + acc[ii][3] * ad3;
#pragma unroll
        for (int o = 16; o; o >>= 1) {
            s += __shfl_xor_sync(0xffffffffu, s, o);
            d += __shfl_xor_sync(0xffffffffu, d, o);
        }
        if (tcol == 0) {
            int row = rowBase + trow + ii;
            g_asrc[row] = s;
            g_adst[row] = d;
        }
    }
}

// Fused kernel: blocks [0,256) do GEMM tiles, blocks [256, 256+8192) do CSR rows.
__global__ void fused_csr_gemm_k(const float* __restrict__ adj,
                                 const float* __restrict__ A,
                                 const float* __restrict__ W,
                                 const float* __restrict__ att_src,
                                 const float* __restrict__ att_dst,
                                 float* __restrict__ C) {
    if (blockIdx.x < GEMM_BLOCKS)
        gemm_body(A, W, att_src, att_dst, C, blockIdx.x * BM);
    else
        csr_body(adj, blockIdx.x - GEMM_BLOCKS);
}

// Layer-1 GEMM (CSR already built)
__global__ void gemm_k(const float* __restrict__ A, const float* __restrict__ W,
                       const float* __restrict__ att_src,
                       const float* __restrict__ att_dst,
                       float* __restrict__ C) {
    gemm_body(A, W, att_src, att_dst, C, blockIdx.x * BM);
}

// ---------------------------------------------------------------------------
// Aggregate: one block (128 thr = 4 warps) per row.
// Warp w handles edges w, w+4, ...; lane owns channels [4*lane, 4*lane+4).
// ---------------------------------------------------------------------------
__global__ void aggregate_k(const float* __restrict__ h,
                            const float* __restrict__ bias,
                            float* __restrict__ out, int doRelu) {
    int i = blockIdx.x;
    int tid = threadIdx.x;
    int warp = tid >> 5, lane = tid & 31;
    __shared__ int    s_col[MAXDEG];
    __shared__ float  s_w[MAXDEG];
    __shared__ float  s_inv;
    __shared__ __align__(16) float4 s_part[3][32];

    int deg = g_deg[i];
    float adsti = g_adst[i];

    // edge scores e = leaky_relu(a_src[j] + a_dst[i])
    for (int j = tid; j < deg; j += 128) {
        int c = g_col[i * MAXDEG + j];
        s_col[j] = c;
        float e = g_asrc[c] + adsti;
        s_w[j] = (e >= 0.f) ? e : 0.2f * e;
    }
    __syncthreads();

    // softmax normalization by warp 0 (shuffle reductions)
    if (warp == 0) {
        float m = -1e30f;
        for (int j = lane; j < deg; j += 32) m = fmaxf(m, s_w[j]);
#pragma unroll
        for (int o = 16; o; o >>= 1) m = fmaxf(m, __shfl_xor_sync(0xffffffffu, m, o));
        float sum = 0.f;
        for (int j = lane; j < deg; j += 32) {
            float w = __expf(s_w[j] - m);
            s_w[j] = w;
            sum += w;
        }
#pragma unroll
        for (int o = 16; o; o >>= 1) sum += __shfl_xor_sync(0xffffffffu, sum, o);
        if (lane == 0) s_inv = 1.0f / sum;
    }
    __syncthreads();

    // weighted gather: float4 per lane, 4 independent accumulators per warp
    float4 a0 = make_float4(0.f, 0.f, 0.f, 0.f);
    float4 a1 = make_float4(0.f, 0.f, 0.f, 0.f);
    float4 a2 = make_float4(0.f, 0.f, 0.f, 0.f);
    float4 a3 = make_float4(0.f, 0.f, 0.f, 0.f);
    int j = warp;
    for (; j + 12 < deg; j += 16) {
        float w0 = s_w[j],     w1 = s_w[j + 4];
        float w2 = s_w[j + 8], w3 = s_w[j + 12];
        int c0 = s_col[j],     c1 = s_col[j + 4];
        int c2 = s_col[j + 8], c3 = s_col[j + 12];
        float4 h0 = *(const float4*)&h[(size_t)c0 * DD + lane * 4];
        float4 h1 = *(const float4*)&h[(size_t)c1 * DD + lane * 4];
        float4 h2 = *(const float4*)&h[(size_t)c2 * DD + lane * 4];
        float4 h3 = *(const float4*)&h[(size_t)c3 * DD + lane * 4];
        a0.x += w0 * h0.x; a0.y += w0 * h0.y; a0.z += w0 * h0.z; a0.w += w0 * h0.w;
        a1.x += w1 * h1.x; a1.y += w1 * h1.y; a1.z += w1 * h1.z; a1.w += w1 * h1.w;
        a2.x += w2 * h2.x; a2.y += w2 * h2.y; a2.z += w2 * h2.z; a2.w += w2 * h2.w;
        a3.x += w3 * h3.x; a3.y += w3 * h3.y; a3.z += w3 * h3.z; a3.w += w3 * h3.w;
    }
    for (; j < deg; j += 4) {
        float w0 = s_w[j];
        float4 h0 = *(const float4*)&h[(size_t)s_col[j] * DD + lane * 4];
        a0.x += w0 * h0.x; a0.y += w0 * h0.y; a0.z += w0 * h0.z; a0.w += w0 * h0.w;
    }
    a0.x += a1.x + a2.x + a3.x;
    a0.y += a1.y + a2.y + a3.y;
    a0.z += a1.z + a2.z + a3.z;
    a0.w += a1.w + a2.w + a3.w;

    if (warp) s_part[warp - 1][lane] = a0;
    __syncthreads();

    if (warp == 0) {
        float4 p0 = s_part[0][lane], p1 = s_part[1][lane], p2 = s_part[2][lane];
        float inv = s_inv;
        float b0v = bias[lane * 4 + 0], b1v = bias[lane * 4 + 1];
        float b2v = bias[lane * 4 + 2], b3v = bias[lane * 4 + 3];
        float4 o;
        o.x = (a0.x + p0.x + p1.x + p2.x) * inv + b0v;
        o.y = (a0.y + p0.y + p1.y + p2.y) * inv + b1v;
        o.z = (a0.z + p0.z + p1.z + p2.z) * inv + b2v;
        o.w = (a0.w + p0.w + p1.w + p2.w) * inv + b3v;
        if (doRelu) {
            o.x = fmaxf(o.x, 0.f); o.y = fmaxf(o.y, 0.f);
            o.z = fmaxf(o.z, 0.f); o.w = fmaxf(o.w, 0.f);
        }
        *(float4*)&out[(size_t)i * DD + lane * 4] = o;
    }
}

// ---------------------------------------------------------------------------
extern "C" void kernel_launch(void* const* d_in, const int* in_sizes, int n_in,
                              void* d_out, int out_size) {
    const float* x        = (const float*)d_in[0];
    const float* adj      = (const float*)d_in[1];
    const float* W0       = (const float*)d_in[2];
    const float* att_src0 = (const float*)d_in[3];
    const float* att_dst0 = (const float*)d_in[4];
    const float* b0       = (const float*)d_in[5];
    const float* W1       = (const float*)d_in[6];
    const float* att_src1 = (const float*)d_in[7];
    const float* att_dst1 = (const float*)d_in[8];
    const float* b1       = (const float*)d_in[9];

    float* out0 = (float*)d_out;                  // [N,128]
    float* out1 = (float*)d_out + (size_t)NN * DD;

    float* h;
    cudaGetSymbolAddress((void**)&h, g_h);

    // Layer 0: CSR build (DRAM-bound, MLP=8) overlapped with GEMM
    fused_csr_gemm_k<<<GEMM_BLOCKS + NN, 256>>>(adj, x, W0, att_src0, att_dst0, h);
    aggregate_k<<<NN, 128>>>(h, b0, out0, /*relu=*/1);

    // Layer 1
    gemm_k<<<GEMM_BLOCKS, 256>>>(out0, W1, att_src1, att_dst1, h);
    aggregate_k<<<NN, 128>>>(h, b1, out1, /*relu=*/0);
}

// round 13
// speedup vs baseline: 1.4143x; 1.1739x over previous
#include <cuda_runtime.h>
#include <cuda_fp16.h>

// DenseGATBlock: 2-layer GAT, N=8192, D=128, heads=1, sparse adj (~1% + self loops).
// R10: h stored ONLY as fp16 (gather bytes halved -> L2 floor ~16us/layer),
//      aggregate back to x2 unroll (regs ~32, occupancy restored).

#define NN 8192
#define DD 128
#define MAXDEG 256
#define BM 32
#define GEMM_BLOCKS (NN / BM)   // 256

// Scratch (device globals; no allocation allowed)
__device__ int   g_col[NN * MAXDEG];              // 8 MB padded neighbor lists
__device__ int   g_deg[NN];
__device__ __align__(16) __half g_h16[NN * DD];   // 2 MB, L2-resident
__device__ float g_asrc[NN];
__device__ float g_adst[NN];

// ---------------------------------------------------------------------------
// CSR build body: one block per row, 256 threads, prefetch 8 float4/thread.
// ---------------------------------------------------------------------------
__device__ __forceinline__ void csr_body(const float* __restrict__ adj, int i) {
    __shared__ int cnt;
    if (threadIdx.x == 0) cnt = 0;
    __syncthreads();
    const float4* row = (const float4*)(adj + (size_t)i * NN);
    int* outc = g_col + i * MAXDEG;
    int tid = threadIdx.x;

    float4 f[8];
#pragma unroll
    for (int k = 0; k < 8; k++) f[k] = row[tid + k * 256];   // MLP=8

#pragma unroll
    for (int k = 0; k < 8; k++) {
        int base = 4 * (tid + k * 256);
        if (f[k].x != 0.f) { int p = atomicAdd(&cnt, 1); if (p < MAXDEG) outc[p] = base; }
        if (f[k].y != 0.f) { int p = atomicAdd(&cnt, 1); if (p < MAXDEG) outc[p] = base + 1; }
        if (f[k].z != 0.f) { int p = atomicAdd(&cnt, 1); if (p < MAXDEG) outc[p] = base + 2; }
        if (f[k].w != 0.f) { int p = atomicAdd(&cnt, 1); if (p < MAXDEG) outc[p] = base + 3; }
    }
    __syncthreads();
    if (threadIdx.x == 0) g_deg[i] = cnt < MAXDEG ? cnt : MAXDEG;
}

// ---------------------------------------------------------------------------
// GEMM body: tile = A@W (fp32 compute), 256 threads, 4x4 register tile.
// Epilogue: fused fp32 attention scores + fp16 h store.
// ---------------------------------------------------------------------------
#define BK 32
__device__ __forceinline__ void gemm_body(const float* __restrict__ A,
                                          const float* __restrict__ W,
                                          const float* __restrict__ att_src,
                                          const float* __restrict__ att_dst,
                                          int rowBase) {
    __shared__ __align__(16) float As[BM][BK];   // 4 KB
    __shared__ __align__(16) float Bs[BK][DD];   // 16 KB
    int tid = threadIdx.x;
    int trow = (tid >> 5) * 4;     // warp -> 4 rows (uniform across warp)
    int tcol = tid & 31;           // 0..31 -> 4 cols
    float acc[4][4];
#pragma unroll
    for (int a = 0; a < 4; a++)
#pragma unroll
        for (int b = 0; b < 4; b++) acc[a][b] = 0.f;

    for (int k0 = 0; k0 < DD; k0 += BK) {
        {
            int r = tid >> 3, cc = (tid & 7) * 4;
            *(float4*)&As[r][cc] =
                *(const float4*)&A[(size_t)(rowBase + r) * DD + k0 + cc];
        }
#pragma unroll
        for (int v = 0; v < 4; v++) {
            int ff = tid + 256 * v;
            int r = ff >> 5, cc = (ff & 31) * 4;
            *(float4*)&Bs[r][cc] = *(const float4*)&W[(k0 + r) * DD + cc];
        }
        __syncthreads();
#pragma unroll
        for (int kk = 0; kk < BK; kk++) {
            float a[4];
#pragma unroll
            for (int ii = 0; ii < 4; ii++) a[ii] = As[trow + ii][kk];
            float4 bv = *(float4*)&Bs[kk][tcol * 4];
#pragma unroll
            for (int ii = 0; ii < 4; ii++) {
                acc[ii][0] += a[ii] * bv.x;
                acc[ii][1] += a[ii] * bv.y;
                acc[ii][2] += a[ii] * bv.z;
                acc[ii][3] += a[ii] * bv.w;
            }
        }
        __syncthreads();
    }

    // write h tile as fp16 (4 halves = 8B per thread-row)
#pragma unroll
    for (int ii = 0; ii < 4; ii++) {
        __half2 lo = __floats2half2_rn(acc[ii][0], acc[ii][1]);
        __half2 hi = __floats2half2_rn(acc[ii][2], acc[ii][3]);
        uint2 pk;
        pk.x = *(unsigned*)&lo;
        pk.y = *(unsigned*)&hi;
        *(uint2*)&g_h16[(size_t)(rowBase + trow + ii) * DD + tcol * 4] = pk;
    }

    // fused fp32 attention scores (scalar att loads: alignment-safe)
    float as0 = att_src[tcol * 4 + 0], as1 = att_src[tcol * 4 + 1];
    float as2 = att_src[tcol * 4 + 2], as3 = att_src[tcol * 4 + 3];
    float ad0 = att_dst[tcol * 4 + 0], ad1 = att_dst[tcol * 4 + 1];
    float ad2 = att_dst[tcol * 4 + 2], ad3 = att_dst[tcol * 4 + 3];
#pragma unroll
    for (int ii = 0; ii < 4; ii++) {
        float s = acc[ii][0] * as0 + acc[ii][1] * as1 +
                  acc[ii][2] * as2 + acc[ii][3] * as3;
        float d = acc[ii][0] * ad0 + acc[ii][1] * ad1 +
                  acc[ii][2] * ad2 + acc[ii][3] * ad3;
#pragma unroll
        for (int o = 16; o; o >>= 1) {
            s += __shfl_xor_sync(0xffffffffu, s, o);
            d += __shfl_xor_sync(0xffffffffu, d, o);
        }
        if (tcol == 0) {
            int row = rowBase + trow + ii;
            g_asrc[row] = s;
            g_adst[row] = d;
        }
    }
}

// Fused kernel: blocks [0,256) GEMM tiles, blocks [256, 256+8192) CSR rows.
__global__ void fused_csr_gemm_k(const float* __restrict__ adj,
                                 const float* __restrict__ A,
                                 const float* __restrict__ W,
                                 const float* __restrict__ att_src,
                                 const float* __restrict__ att_dst) {
    if (blockIdx.x < GEMM_BLOCKS)
        gemm_body(A, W, att_src, att_dst, blockIdx.x * BM);
    else
        csr_body(adj, blockIdx.x - GEMM_BLOCKS);
}

// Layer-1 GEMM (CSR already built)
__global__ void gemm_k(const float* __restrict__ A, const float* __restrict__ W,
                       const float* __restrict__ att_src,
                       const float* __restrict__ att_dst) {
    gemm_body(A, W, att_src, att_dst, blockIdx.x * BM);
}

// ---------------------------------------------------------------------------
// Aggregate: one block (128 thr = 4 warps) per row; fp16 h gather.
// Warp w handles edges w, w+4, ...; lane owns channels [4*lane, 4*lane+4).
// ---------------------------------------------------------------------------
__global__ void aggregate_k(const float* __restrict__ bias,
                            float* __restrict__ out, int doRelu) {
    int i = blockIdx.x;
    int tid = threadIdx.x;
    int warp = tid >> 5, lane = tid & 31;
    __shared__ int    s_col[MAXDEG];
    __shared__ float  s_w[MAXDEG];
    __shared__ float  s_inv;
    __shared__ __align__(16) float4 s_part[3][32];

    int deg = g_deg[i];
    float adsti = g_adst[i];

    // edge scores e = leaky_relu(a_src[j] + a_dst[i])
    for (int j = tid; j < deg; j += 128) {
        int c = g_col[i * MAXDEG + j];
        s_col[j] = c;
        float e = g_asrc[c] + adsti;
        s_w[j] = (e >= 0.f) ? e : 0.2f * e;
    }
    __syncthreads();

    // softmax normalization by warp 0 (shuffle reductions)
    if (warp == 0) {
        float m = -1e30f;
        for (int j = lane; j < deg; j += 32) m = fmaxf(m, s_w[j]);
#pragma unroll
        for (int o = 16; o; o >>= 1) m = fmaxf(m, __shfl_xor_sync(0xffffffffu, m, o));
        float sum = 0.f;
        for (int j = lane; j < deg; j += 32) {
            float w = __expf(s_w[j] - m);
            s_w[j] = w;
            sum += w;
        }
#pragma unroll
        for (int o = 16; o; o >>= 1) sum += __shfl_xor_sync(0xffffffffu, sum, o);
        if (lane == 0) s_inv = 1.0f / sum;
    }
    __syncthreads();

    // weighted gather: half4 (8B) per lane per edge, 2 independent accumulators
    float4 a0 = make_float4(0.f, 0.f, 0.f, 0.f);
    float4 a1 = make_float4(0.f, 0.f, 0.f, 0.f);
    int j = warp;
    for (; j + 4 < deg; j += 8) {
        float w0 = s_w[j], w1 = s_w[j + 4];
        int   c0 = s_col[j], c1 = s_col[j + 4];
        uint2 r0 = *(const uint2*)&g_h16[(size_t)c0 * DD + lane * 4];
        uint2 r1 = *(const uint2*)&g_h16[(size_t)c1 * DD + lane * 4];
        float2 f0a = __half22float2(*(__half2*)&r0.x);
        float2 f0b = __half22float2(*(__half2*)&r0.y);
        float2 f1a = __half22float2(*(__half2*)&r1.x);
        float2 f1b = __half22float2(*(__half2*)&r1.y);
        a0.x += w0 * f0a.x; a0.y += w0 * f0a.y; a0.z += w0 * f0b.x; a0.w += w0 * f0b.y;
        a1.x += w1 * f1a.x; a1.y += w1 * f1a.y; a1.z += w1 * f1b.x; a1.w += w1 * f1b.y;
    }
    if (j < deg) {
        float w0 = s_w[j];
        uint2 r0 = *(const uint2*)&g_h16[(size_t)s_col[j] * DD + lane * 4];
        float2 f0a = __half22float2(*(__half2*)&r0.x);
        float2 f0b = __half22float2(*(__half2*)&r0.y);
        a0.x += w0 * f0a.x; a0.y += w0 * f0a.y; a0.z += w0 * f0b.x; a0.w += w0 * f0b.y;
    }
    a0.x += a1.x; a0.y += a1.y; a0.z += a1.z; a0.w += a1.w;

    if (warp) s_part[warp - 1][lane] = a0;
    __syncthreads();

    if (warp == 0) {
        float4 p0 = s_part[0][lane], p1 = s_part[1][lane], p2 = s_part[2][lane];
        float inv = s_inv;
        float b0v = bias[lane * 4 + 0], b1v = bias[lane * 4 + 1];
        float b2v = bias[lane * 4 + 2], b3v = bias[lane * 4 + 3];
        float4 o;
        o.x = (a0.x + p0.x + p1.x + p2.x) * inv + b0v;
        o.y = (a0.y + p0.y + p1.y + p2.y) * inv + b1v;
        o.z = (a0.z + p0.z + p1.z + p2.z) * inv + b2v;
        o.w = (a0.w + p0.w + p1.w + p2.w) * inv + b3v;
        if (doRelu) {
            o.x = fmaxf(o.x, 0.f); o.y = fmaxf(o.y, 0.f);
            o.z = fmaxf(o.z, 0.f); o.w = fmaxf(o.w, 0.f);
        }
        *(float4*)&out[(size_t)i * DD + lane * 4] = o;
    }
}

// ---------------------------------------------------------------------------
extern "C" void kernel_launch(void* const* d_in, const int* in_sizes, int n_in,
                              void* d_out, int out_size) {
    const float* x        = (const float*)d_in[0];
    const float* adj      = (const float*)d_in[1];
    const float* W0       = (const float*)d_in[2];
    const float* att_src0 = (const float*)d_in[3];
    const float* att_dst0 = (const float*)d_in[4];
    const float* b0       = (const float*)d_in[5];
    const float* W1       = (const float*)d_in[6];
    const float* att_src1 = (const float*)d_in[7];
    const float* att_dst1 = (const float*)d_in[8];
    const float* b1       = (const float*)d_in[9];

    float* out0 = (float*)d_out;                  // [N,128]
    float* out1 = (float*)d_out + (size_t)NN * DD;

    // Layer 0: CSR build (DRAM-bound, MLP=8) overlapped with GEMM
    fused_csr_gemm_k<<<GEMM_BLOCKS + NN, 256>>>(adj, x, W0, att_src0, att_dst0);
    aggregate_k<<<NN, 128>>>(b0, out0, /*relu=*/1);

    // Layer 1
    gemm_k<<<GEMM_BLOCKS, 256>>>(out0, W1, att_src1, att_dst1);
    aggregate_k<<<NN, 128>>>(b1, out1, /*relu=*/0);
}

// round 14
// speedup vs baseline: 1.5297x; 1.0816x over previous
#include <cuda_runtime.h>
#include <cuda_fp16.h>

// DenseGATBlock: 2-layer GAT, N=8192, D=128, heads=1, sparse adj (~1% + self loops).
// R13: warp-per-row aggregate (no block barriers, all-shuffle softmax, full occ).
//      GEMM + fused CSR kernels unchanged from the passing R10.

#define NN 8192
#define DD 128
#define MAXDEG 256
#define BM 32
#define GEMM_BLOCKS (NN / BM)   // 256

// Scratch (device globals; no allocation allowed)
__device__ int   g_col[NN * MAXDEG];              // 8 MB padded neighbor lists
__device__ int   g_deg[NN];
__device__ __align__(16) __half g_h16[NN * DD];   // 2 MB, L2-resident
__device__ float g_asrc[NN];
__device__ float g_adst[NN];

// ---------------------------------------------------------------------------
// CSR build body: one block per row, 256 threads, prefetch 8 float4/thread.
// ---------------------------------------------------------------------------
__device__ __forceinline__ void csr_body(const float* __restrict__ adj, int i) {
    __shared__ int cnt;
    if (threadIdx.x == 0) cnt = 0;
    __syncthreads();
    const float4* row = (const float4*)(adj + (size_t)i * NN);
    int* outc = g_col + i * MAXDEG;
    int tid = threadIdx.x;

    float4 f[8];
#pragma unroll
    for (int k = 0; k < 8; k++) f[k] = __ldcs(&row[tid + k * 256]);   // MLP=8, streaming

#pragma unroll
    for (int k = 0; k < 8; k++) {
        int base = 4 * (tid + k * 256);
        if (f[k].x != 0.f) { int p = atomicAdd(&cnt, 1); if (p < MAXDEG) outc[p] = base; }
        if (f[k].y != 0.f) { int p = atomicAdd(&cnt, 1); if (p < MAXDEG) outc[p] = base + 1; }
        if (f[k].z != 0.f) { int p = atomicAdd(&cnt, 1); if (p < MAXDEG) outc[p] = base + 2; }
        if (f[k].w != 0.f) { int p = atomicAdd(&cnt, 1); if (p < MAXDEG) outc[p] = base + 3; }
    }
    __syncthreads();
    if (threadIdx.x == 0) g_deg[i] = cnt < MAXDEG ? cnt : MAXDEG;
}

// ---------------------------------------------------------------------------
// GEMM body: tile = A@W (fp32 compute), 256 threads, 4x4 register tile.
// Epilogue: fused fp32 attention scores + fp16 h store.
// ---------------------------------------------------------------------------
#define BK 32
__device__ __forceinline__ void gemm_body(const float* __restrict__ A,
                                          const float* __restrict__ W,
                                          const float* __restrict__ att_src,
                                          const float* __restrict__ att_dst,
                                          int rowBase) {
    __shared__ __align__(16) float As[BM][BK];   // 4 KB
    __shared__ __align__(16) float Bs[BK][DD];   // 16 KB
    int tid = threadIdx.x;
    int trow = (tid >> 5) * 4;     // warp -> 4 rows (uniform across warp)
    int tcol = tid & 31;           // 0..31 -> 4 cols
    float acc[4][4];
#pragma unroll
    for (int a = 0; a < 4; a++)
#pragma unroll
        for (int b = 0; b < 4; b++) acc[a][b] = 0.f;

    for (int k0 = 0; k0 < DD; k0 += BK) {
        {
            int r = tid >> 3, cc = (tid & 7) * 4;
            *(float4*)&As[r][cc] =
                *(const float4*)&A[(size_t)(rowBase + r) * DD + k0 + cc];
        }
#pragma unroll
        for (int v = 0; v < 4; v++) {
            int ff = tid + 256 * v;
            int r = ff >> 5, cc = (ff & 31) * 4;
            *(float4*)&Bs[r][cc] = *(const float4*)&W[(k0 + r) * DD + cc];
        }
        __syncthreads();
#pragma unroll
        for (int kk = 0; kk < BK; kk++) {
            float a[4];
#pragma unroll
            for (int ii = 0; ii < 4; ii++) a[ii] = As[trow + ii][kk];
            float4 bv = *(float4*)&Bs[kk][tcol * 4];
#pragma unroll
            for (int ii = 0; ii < 4; ii++) {
                acc[ii][0] += a[ii] * bv.x;
                acc[ii][1] += a[ii] * bv.y;
                acc[ii][2] += a[ii] * bv.z;
                acc[ii][3] += a[ii] * bv.w;
            }
        }
        __syncthreads();
    }

    // write h tile as fp16 (4 halves = 8B per thread-row)
#pragma unroll
    for (int ii = 0; ii < 4; ii++) {
        __half2 lo = __floats2half2_rn(acc[ii][0], acc[ii][1]);
        __half2 hi = __floats2half2_rn(acc[ii][2], acc[ii][3]);
        uint2 pk;
        pk.x = *(unsigned*)&lo;
        pk.y = *(unsigned*)&hi;
        *(uint2*)&g_h16[(size_t)(rowBase + trow + ii) * DD + tcol * 4] = pk;
    }

    // fused fp32 attention scores (scalar att loads: alignment-safe)
    float as0 = att_src[tcol * 4 + 0], as1 = att_src[tcol * 4 + 1];
    float as2 = att_src[tcol * 4 + 2], as3 = att_src[tcol * 4 + 3];
    float ad0 = att_dst[tcol * 4 + 0], ad1 = att_dst[tcol * 4 + 1];
    float ad2 = att_dst[tcol * 4 + 2], ad3 = att_dst[tcol * 4 + 3];
#pragma unroll
    for (int ii = 0; ii < 4; ii++) {
        float s = acc[ii][0] * as0 + acc[ii][1] * as1 +
                  acc[ii][2] * as2 + acc[ii][3] * as3;
        float d = acc[ii][0] * ad0 + acc[ii][1] * ad1 +
                  acc[ii][2] * ad2 + acc[ii][3] * ad3;
#pragma unroll
        for (int o = 16; o; o >>= 1) {
            s += __shfl_xor_sync(0xffffffffu, s, o);
            d += __shfl_xor_sync(0xffffffffu, d, o);
        }
        if (tcol == 0) {
            int row = rowBase + trow + ii;
            g_asrc[row] = s;
            g_adst[row] = d;
        }
    }
}

// Fused kernel: blocks [0,256) GEMM tiles, blocks [256, 256+8192) CSR rows.
__global__ void fused_csr_gemm_k(const float* __restrict__ adj,
                                 const float* __restrict__ A,
                                 const float* __restrict__ W,
                                 const float* __restrict__ att_src,
                                 const float* __restrict__ att_dst) {
    if (blockIdx.x < GEMM_BLOCKS)
        gemm_body(A, W, att_src, att_dst, blockIdx.x * BM);
    else
        csr_body(adj, blockIdx.x - GEMM_BLOCKS);
}

// Layer-1 GEMM (CSR already built)
__global__ void gemm_k(const float* __restrict__ A, const float* __restrict__ W,
                       const float* __restrict__ att_src,
                       const float* __restrict__ att_dst) {
    gemm_body(A, W, att_src, att_dst, blockIdx.x * BM);
}

// ---------------------------------------------------------------------------
// Aggregate: WARP-PER-ROW. 256 threads = 8 warps = 8 rows per block.
// Lane owns channels [4*lane, 4*lane+4); per-warp shuffle softmax; no block
// barriers, no idle warps. Grid = NN/8.
// ---------------------------------------------------------------------------
__global__ __launch_bounds__(256, 8)
void aggregate_k(const float* __restrict__ bias,
                 float* __restrict__ out, int doRelu) {
    __shared__ float s_w[8][MAXDEG];   // 8 KB
    __shared__ int   s_c[8][MAXDEG];   // 8 KB
    int warp = threadIdx.x >> 5;
    int lane = threadIdx.x & 31;
    int i = blockIdx.x * 8 + warp;

    int deg = g_deg[i];
    float adsti = g_adst[i];
    float* swp = s_w[warp];
    int*   scp = s_c[warp];

    // Phase A: edge scores + per-warp softmax (shuffle reductions)
    float m = -1e30f;
    for (int j = lane; j < deg; j += 32) {
        int c = g_col[i * MAXDEG + j];
        float e = g_asrc[c] + adsti;
        e = (e >= 0.f) ? e : 0.2f * e;
        scp[j] = c;
        swp[j] = e;
        m = fmaxf(m, e);
    }
#pragma unroll
    for (int o = 16; o; o >>= 1) m = fmaxf(m, __shfl_xor_sync(0xffffffffu, m, o));
    float sum = 0.f;
    for (int j = lane; j < deg; j += 32) {
        float w = __expf(swp[j] - m);
        swp[j] = w;
        sum += w;
    }
#pragma unroll
    for (int o = 16; o; o >>= 1) sum += __shfl_xor_sync(0xffffffffu, sum, o);
    float inv = 1.0f / sum;
    __syncwarp();

    // Phase B: weighted gather, half4 (8B) per lane per edge, 2 indep accumulators
    float4 a0 = make_float4(0.f, 0.f, 0.f, 0.f);
    float4 a1 = make_float4(0.f, 0.f, 0.f, 0.f);
    int j = 0;
    for (; j + 1 < deg; j += 2) {
        float w0 = swp[j], w1 = swp[j + 1];      // LDS broadcast
        int   c0 = scp[j], c1 = scp[j + 1];
        uint2 r0 = *(const uint2*)&g_h16[(size_t)c0 * DD + lane * 4];
        uint2 r1 = *(const uint2*)&g_h16[(size_t)c1 * DD + lane * 4];
        float2 f0a = __half22float2(*(__half2*)&r0.x);
        float2 f0b = __half22float2(*(__half2*)&r0.y);
        float2 f1a = __half22float2(*(__half2*)&r1.x);
        float2 f1b = __half22float2(*(__half2*)&r1.y);
        a0.x += w0 * f0a.x; a0.y += w0 * f0a.y; a0.z += w0 * f0b.x; a0.w += w0 * f0b.y;
        a1.x += w1 * f1a.x; a1.y += w1 * f1a.y; a1.z += w1 * f1b.x; a1.w += w1 * f1b.y;
    }
    if (j < deg) {
        float w0 = swp[j];
        uint2 r0 = *(const uint2*)&g_h16[(size_t)scp[j] * DD + lane * 4];
        float2 f0a = __half22float2(*(__half2*)&r0.x);
        float2 f0b = __half22float2(*(__half2*)&r0.y);
        a0.x += w0 * f0a.x; a0.y += w0 * f0a.y; a0.z += w0 * f0b.x; a0.w += w0 * f0b.y;
    }

    float b0v = bias[lane * 4 + 0], b1v = bias[lane * 4 + 1];
    float b2v = bias[lane * 4 + 2], b3v = bias[lane * 4 + 3];
    float4 o;
    o.x = (a0.x + a1.x) * inv + b0v;
    o.y = (a0.y + a1.y) * inv + b1v;
    o.z = (a0.z + a1.z) * inv + b2v;
    o.w = (a0.w + a1.w) * inv + b3v;
    if (doRelu) {
        o.x = fmaxf(o.x, 0.f); o.y = fmaxf(o.y, 0.f);
        o.z = fmaxf(o.z, 0.f); o.w = fmaxf(o.w, 0.f);
    }
    *(float4*)&out[(size_t)i * DD + lane * 4] = o;
}

// ---------------------------------------------------------------------------
extern "C" void kernel_launch(void* const* d_in, const int* in_sizes, int n_in,
                              void* d_out, int out_size) {
    const float* x        = (const float*)d_in[0];
    const float* adj      = (const float*)d_in[1];
    const float* W0       = (const float*)d_in[2];
    const float* att_src0 = (const float*)d_in[3];
    const float* att_dst0 = (const float*)d_in[4];
    const float* b0       = (const float*)d_in[5];
    const float* W1       = (const float*)d_in[6];
    const float* att_src1 = (const float*)d_in[7];
    const float* att_dst1 = (const float*)d_in[8];
    const float* b1       = (const float*)d_in[9];

    float* out0 = (float*)d_out;                  // [N,128]
    float* out1 = (float*)d_out + (size_t)NN * DD;

    // Layer 0: CSR build (DRAM-bound, MLP=8) overlapped with GEMM
    fused_csr_gemm_k<<<GEMM_BLOCKS + NN, 256>>>(adj, x, W0, att_src0, att_dst0);
    aggregate_k<<<NN / 8, 256>>>(b0, out0, /*relu=*/1);

    // Layer 1
    gemm_k<<<GEMM_BLOCKS, 256>>>(out0, W1, att_src1, att_dst1);
    aggregate_k<<<NN / 8, 256>>>(b1, out1, /*relu=*/0);
}